// round 4
// baseline (speedup 1.0000x reference)
#include <cuda_runtime.h>
#include <cstdint>

#define HW    65536
#define NQ    100
#define NT    32
#define NB    8
#define NROWP 112   // 7 mtiles * 16

// ---------------- device scratch (no allocations allowed) ----------------
__device__ uint32_t g_bits[NB * HW];          // per-pixel word, bit t = tm[b][t][pixel]
__device__ float    g_tsum[NB * NT];          // sum of tm per (b,t)
__device__ float    g_dotPM[NB * NROWP * NT]; // sum pm * tm
__device__ float    g_dotSIG[NB * NROWP * NT];// sum sigmoid(pm) * tm
__device__ float    g_sumSP[NB * NROWP];      // sum softplus(pm) per (b,n)
__device__ float    g_sumSIG[NB * NROWP];     // sum sigmoid(pm) per (b,n)
__device__ float    g_classT[NB * NT * NQ];   // class cost, layout [b][t][n]
__device__ float    g_costT[NB * NT * NQ];    // total cost, layout [b][t][n]

// ---------------- helpers ----------------
__device__ __forceinline__ uint32_t pack_bf16(float hi, float lo) {
    uint32_t d;
    asm("cvt.rn.bf16x2.f32 %0, %1, %2;" : "=r"(d) : "f"(hi), "f"(lo));
    return d;
}

__device__ __forceinline__ void mma_bf16(float* c, const uint32_t* a,
                                         uint32_t b0, uint32_t b1) {
    asm volatile(
        "mma.sync.aligned.m16n8k16.row.col.f32.bf16.bf16.f32 "
        "{%0,%1,%2,%3}, {%4,%5,%6,%7}, {%8,%9}, {%0,%1,%2,%3};"
        : "+f"(c[0]), "+f"(c[1]), "+f"(c[2]), "+f"(c[3])
        : "r"(a[0]), "r"(a[1]), "r"(a[2]), "r"(a[3]), "r"(b0), "r"(b1));
}

__device__ __forceinline__ void elem_math(float x, float& sig, float& sp) {
    float ax  = fabsf(x);
    float e   = __expf(-ax);          // MUFU.EX2 (+ scale)
    float ope = 1.0f + e;
    float r   = __fdividef(1.0f, ope); // MUFU.RCP
    sig = (x >= 0.0f) ? r : 1.0f - r;
    sp  = fmaxf(x, 0.0f) + __logf(ope); // MUFU.LG2 (+ scale)
}

// ---------------- kernel 0: zero accumulators ----------------
__global__ void k_zero() {
    int i = blockIdx.x * 256 + threadIdx.x;
    if (i < NB * NROWP * NT) { g_dotPM[i] = 0.f; g_dotSIG[i] = 0.f; }
    if (i < NB * NROWP)      { g_sumSP[i] = 0.f; g_sumSIG[i] = 0.f; }
    if (i < NB * NT)         { g_tsum[i] = 0.f; }
}

// ---------------- kernel 1: class cost ----------------
__global__ void k_class(const float* __restrict__ logits,
                        const int* __restrict__ labels) {
    int b = blockIdx.x / NQ, n = blockIdx.x % NQ;
    int lane = threadIdx.x;
    __shared__ float sh[81];
    const float* L = logits + (size_t)(b * NQ + n) * 81;

    float x0 = L[lane];
    float x1 = (lane + 32 < 81) ? L[lane + 32] : -1e30f;
    float x2 = (lane + 64 < 81) ? L[lane + 64] : -1e30f;
    float m = fmaxf(x0, fmaxf(x1, x2));
    #pragma unroll
    for (int o = 16; o; o >>= 1) m = fmaxf(m, __shfl_xor_sync(0xffffffffu, m, o));

    float e0 = __expf(x0 - m);
    float e1 = (lane + 32 < 81) ? __expf(x1 - m) : 0.f;
    float e2 = (lane + 64 < 81) ? __expf(x2 - m) : 0.f;
    float s = e0 + e1 + e2;
    #pragma unroll
    for (int o = 16; o; o >>= 1) s += __shfl_xor_sync(0xffffffffu, s, o);

    sh[lane] = e0;
    if (lane + 32 < 81) sh[lane + 32] = e1;
    if (lane + 64 < 81) sh[lane + 64] = e2;
    __syncwarp();

    float inv = 1.0f / s;
    int lbl = labels[b * NT + lane];   // lane == t, labels in [0,80)
    g_classT[(b * NT + lane) * NQ + n] = -sh[lbl] * inv;
}

// ---------------- kernel 2: target mask preprocess ----------------
__global__ __launch_bounds__(256) void k_tmask(const float* __restrict__ tgt) {
    int b = blockIdx.y;
    int p = blockIdx.x * 256 + threadIdx.x;   // pixel index in 256x256
    int h = p >> 8, wc = p & 255;
    size_t base = ((size_t)b * NT) * 512 * 512 + (size_t)(2 * h) * 512 + 2 * wc;
    uint32_t word = 0;
    #pragma unroll
    for (int t = 0; t < 32; ++t) {
        float v = tgt[base + (size_t)t * 512 * 512];
        word |= (v != 0.0f ? 1u : 0u) << t;
    }
    g_bits[b * HW + p] = word;

    int lane = threadIdx.x & 31;
    int cnt = 0;
    #pragma unroll
    for (int t = 0; t < 32; ++t) {
        unsigned m = __ballot_sync(0xffffffffu, (word >> t) & 1u);
        if (lane == t) cnt = __popc(m);
    }
    atomicAdd(&g_tsum[b * NT + lane], (float)cnt);
}

// ---------------- kernel 3: fused elementwise + dual bf16 MMA ----------------
__global__ __launch_bounds__(256) void k_main(const float* __restrict__ pm) {
    const int b = blockIdx.z, mt = blockIdx.y;
    const int warp = threadIdx.x >> 5, lane = threadIdx.x & 31;
    const int kstart = blockIdx.x * (HW / 16) + warp * (HW / 16 / 8); // 512-pixel slice
    const int rq = lane >> 2;        // 0..7
    const int kq = (lane & 3) << 1;  // 0,2,4,6
    const int r_lo = mt * 16 + rq, r_hi = r_lo + 8;
    const int rl = min(r_lo, NQ - 1), rh = min(r_hi, NQ - 1);

    const float*    pmb = pm + (size_t)b * NQ * HW;
    const uint32_t* bw  = g_bits + b * HW;

    float cpm[4][4], csg[4][4];
    #pragma unroll
    for (int i = 0; i < 4; ++i)
        #pragma unroll
        for (int j = 0; j < 4; ++j) { cpm[i][j] = 0.f; csg[i][j] = 0.f; }

    float ssp0 = 0.f, ssp1 = 0.f, ssg0 = 0.f, ssg1 = 0.f;

    #pragma unroll 4
    for (int it = 0; it < 32; ++it) {
        int k0 = kstart + it * 16 + kq;
        float2 x00 = *(const float2*)(pmb + (size_t)rl * HW + k0);
        float2 x10 = *(const float2*)(pmb + (size_t)rh * HW + k0);
        float2 x01 = *(const float2*)(pmb + (size_t)rl * HW + k0 + 8);
        float2 x11 = *(const float2*)(pmb + (size_t)rh * HW + k0 + 8);

        float s00a, s00b, s10a, s10b, s01a, s01b, s11a, s11b;
        float p00a, p00b, p10a, p10b, p01a, p01b, p11a, p11b;
        elem_math(x00.x, s00a, p00a); elem_math(x00.y, s00b, p00b);
        elem_math(x10.x, s10a, p10a); elem_math(x10.y, s10b, p10b);
        elem_math(x01.x, s01a, p01a); elem_math(x01.y, s01b, p01b);
        elem_math(x11.x, s11a, p11a); elem_math(x11.y, s11b, p11b);

        ssp0 += (p00a + p00b) + (p01a + p01b);
        ssp1 += (p10a + p10b) + (p11a + p11b);
        ssg0 += (s00a + s00b) + (s01a + s01b);
        ssg1 += (s10a + s10b) + (s11a + s11b);

        uint32_t apm[4] = { pack_bf16(x00.y, x00.x), pack_bf16(x10.y, x10.x),
                            pack_bf16(x01.y, x01.x), pack_bf16(x11.y, x11.x) };
        uint32_t asg[4] = { pack_bf16(s00b, s00a), pack_bf16(s10b, s10a),
                            pack_bf16(s01b, s01a), pack_bf16(s11b, s11a) };

        uint32_t w0 = bw[k0], w1 = bw[k0 + 1], w2 = bw[k0 + 8], w3 = bw[k0 + 9];
        #pragma unroll
        for (int nt = 0; nt < 4; ++nt) {
            int n = rq + nt * 8;
            uint32_t b0 = ((w0 >> n) & 1u) * 0x3F80u | ((w1 >> n) & 1u) * 0x3F800000u;
            uint32_t b1 = ((w2 >> n) & 1u) * 0x3F80u | ((w3 >> n) & 1u) * 0x3F800000u;
            mma_bf16(cpm[nt], apm, b0, b1);
            mma_bf16(csg[nt], asg, b0, b1);
        }
    }

    int base_lo = (b * NROWP + r_lo) * NT;
    int base_hi = (b * NROWP + r_hi) * NT;
    #pragma unroll
    for (int nt = 0; nt < 4; ++nt) {
        int c = nt * 8 + kq;
        atomicAdd(&g_dotPM[base_lo + c],     cpm[nt][0]);
        atomicAdd(&g_dotPM[base_lo + c + 1], cpm[nt][1]);
        atomicAdd(&g_dotPM[base_hi + c],     cpm[nt][2]);
        atomicAdd(&g_dotPM[base_hi + c + 1], cpm[nt][3]);
        atomicAdd(&g_dotSIG[base_lo + c],     csg[nt][0]);
        atomicAdd(&g_dotSIG[base_lo + c + 1], csg[nt][1]);
        atomicAdd(&g_dotSIG[base_hi + c],     csg[nt][2]);
        atomicAdd(&g_dotSIG[base_hi + c + 1], csg[nt][3]);
    }
    atomicAdd(&g_sumSP[b * NROWP + r_lo],  ssp0);
    atomicAdd(&g_sumSP[b * NROWP + r_hi],  ssp1);
    atomicAdd(&g_sumSIG[b * NROWP + r_lo], ssg0);
    atomicAdd(&g_sumSIG[b * NROWP + r_hi], ssg1);
}

// ---------------- kernel 4: assemble transposed cost matrix ----------------
__global__ void k_cost() {
    int i = blockIdx.x * 256 + threadIdx.x;
    if (i >= NB * NT * NQ) return;
    int n = i % NQ;
    int t = (i / NQ) % NT;
    int b = i / (NQ * NT);
    float spm  = g_sumSP[b * NROWP + n] * (1.0f / HW);
    float dpm  = g_dotPM[(b * NROWP + n) * NT + t] * (1.0f / HW);
    float dsg  = g_dotSIG[(b * NROWP + n) * NT + t];
    float den  = g_sumSIG[b * NROWP + n] + g_tsum[b * NT + t] + 1.0f;
    float dice = 1.0f - (2.0f * dsg + 1.0f) / den;
    g_costT[i] = g_classT[i] + (spm - dpm) + dice;   // [b][t][n]
}

// ---------------- kernel 5: Hungarian (JV), one warp per batch ----------------
// Output written as FLOAT32 values (harness __output__ dtype hypothesis:
// integer indices canonicalized to float32; indices 0..99 are exact in fp32).
__global__ void k_hung(float* __restrict__ out) {
    int b = blockIdx.x;
    int lane = threadIdx.x;
    __shared__ double u[33], v[101], minv[101];
    __shared__ int p[101], way[101], used[101];
    const float* Cb = g_costT + b * NT * NQ;  // [32 rows][100 cols]

    for (int j = lane; j < 101; j += 32) { v[j] = 0.0; p[j] = 0; }
    for (int j = lane; j < 33; j += 32) u[j] = 0.0;
    __syncwarp();

    for (int i = 1; i <= NT; ++i) {
        for (int j = lane; j < 101; j += 32) { minv[j] = 1e300; used[j] = 0; }
        if (lane == 0) p[0] = i;
        __syncwarp();

        int j0 = 0;
        while (true) {
            if (lane == 0) used[j0] = 1;
            __syncwarp();
            int i0 = p[j0];
            double ui0 = u[i0];

            double bv = 1e301; int bj = 127;
            for (int j = lane; j < 101; j += 32) {
                if (j >= 1 && !used[j]) {
                    double cur = (double)Cb[(i0 - 1) * NQ + (j - 1)] - ui0 - v[j];
                    if (cur < minv[j]) { minv[j] = cur; way[j] = j0; }
                    double mv = minv[j];
                    if (mv < bv || (mv == bv && j < bj)) { bv = mv; bj = j; }
                }
            }
            #pragma unroll
            for (int o = 16; o; o >>= 1) {
                double ov = __shfl_xor_sync(0xffffffffu, bv, o);
                int    oj = __shfl_xor_sync(0xffffffffu, bj, o);
                if (ov < bv || (ov == bv && oj < bj)) { bv = ov; bj = oj; }
            }
            double delta = bv; int j1 = bj;

            for (int j = lane; j < 101; j += 32) {
                if (used[j]) { u[p[j]] += delta; v[j] -= delta; }
                else if (j >= 1) minv[j] -= delta;
            }
            __syncwarp();
            j0 = j1;
            if (p[j0] == 0) break;
        }
        if (lane == 0) {
            int jj = j0;
            while (jj) { int jn = way[jj]; p[jj] = p[jn]; jj = jn; }
        }
        __syncwarp();
    }

    if (lane == 0) {
        int k = 0;
        for (int j = 1; j <= NQ; ++j) {
            if (p[j]) {
                out[b * NT + k]            = (float)(j - 1);     // src (query idx)
                out[NB * NT + b * NT + k]  = (float)(p[j] - 1);  // tgt (target idx)
                ++k;
            }
        }
    }
}

// ---------------- launch ----------------
// Bind inputs by ELEMENT COUNT, not position (robust to metadata ordering):
//   pred_logits   8*100*81        = 64800
//   pred_masks    8*100*256*256   = 52428800
//   target_masks  8*32*512*512    = 67108864
//   target_labels 8*32            = 256
extern "C" void kernel_launch(void* const* d_in, const int* in_sizes, int n_in,
                              void* d_out, int out_size) {
    const float* logits = nullptr;
    const float* pmask  = nullptr;
    const float* tmask  = nullptr;
    const int*   labels = nullptr;

    for (int i = 0; i < n_in; ++i) {
        switch (in_sizes[i]) {
            case 64800:    logits = (const float*)d_in[i]; break;
            case 52428800: pmask  = (const float*)d_in[i]; break;
            case 256:      labels = (const int*)d_in[i];   break;
            default:
                if (in_sizes[i] == 67108864) tmask = (const float*)d_in[i];
                break;
        }
    }
    float* out = (float*)d_out;   // [2,8,32] as float32 values

    k_zero<<<(NB * NROWP * NT + 255) / 256, 256>>>();
    k_class<<<NB * NQ, 32>>>(logits, labels);
    k_tmask<<<dim3(HW / 256, NB), 256>>>(tmask);
    k_main<<<dim3(16, 7, NB), 256>>>(pmask);
    k_cost<<<(NB * NT * NQ + 255) / 256, 256>>>();
    k_hung<<<NB, 32>>>(out);
}

// round 5
// speedup vs baseline: 1.6951x; 1.6951x over previous
#include <cuda_runtime.h>
#include <cstdint>

#define HW    65536
#define NQ    100
#define NT    32
#define NB    8
#define NROWP 112   // 7 mtiles * 16

// ---------------- device scratch ----------------
__device__ uint32_t g_bits[NB * HW];
__device__ float    g_tsum[NB * NT];
__device__ float    g_dotPM[NB * NROWP * NT];
__device__ float    g_dotSIG[NB * NROWP * NT];
__device__ float    g_sumSP[NB * NROWP];
__device__ float    g_sumSIG[NB * NROWP];
__device__ float    g_classT[NB * NT * NQ];
__device__ float    g_costT[NB * NT * NQ];   // [b][t][n]

// ---------------- helpers ----------------
__device__ __forceinline__ uint32_t pack_bf16(float hi, float lo) {
    uint32_t d;
    asm("cvt.rn.bf16x2.f32 %0, %1, %2;" : "=r"(d) : "f"(hi), "f"(lo));
    return d;
}

__device__ __forceinline__ void mma_bf16(float* c, const uint32_t* a,
                                         uint32_t b0, uint32_t b1) {
    asm volatile(
        "mma.sync.aligned.m16n8k16.row.col.f32.bf16.bf16.f32 "
        "{%0,%1,%2,%3}, {%4,%5,%6,%7}, {%8,%9}, {%0,%1,%2,%3};"
        : "+f"(c[0]), "+f"(c[1]), "+f"(c[2]), "+f"(c[3])
        : "r"(a[0]), "r"(a[1]), "r"(a[2]), "r"(a[3]), "r"(b0), "r"(b1));
}

__device__ __forceinline__ void elem_math(float x, float& sig, float& sp) {
    float ax  = fabsf(x);
    float e   = __expf(-ax);
    float ope = 1.0f + e;
    float r   = __fdividef(1.0f, ope);
    sig = (x >= 0.0f) ? r : 1.0f - r;
    sp  = fmaxf(x, 0.0f) + __logf(ope);
}

// order-preserving float<->uint32 key (total order incl. negatives)
__device__ __forceinline__ uint32_t fkey(float f) {
    uint32_t u = __float_as_uint(f);
    return (u & 0x80000000u) ? ~u : (u | 0x80000000u);
}
__device__ __forceinline__ float fkey_inv(uint32_t k) {
    uint32_t u = (k & 0x80000000u) ? (k ^ 0x80000000u) : ~k;
    return __uint_as_float(u);
}
__device__ __forceinline__ int sel4i(int a0, int a1, int a2, int a3, int s) {
    return s == 0 ? a0 : s == 1 ? a1 : s == 2 ? a2 : a3;
}

// ---------------- kernel 0: zero accumulators ----------------
__global__ void k_zero() {
    int i = blockIdx.x * 256 + threadIdx.x;
    if (i < NB * NROWP * NT) { g_dotPM[i] = 0.f; g_dotSIG[i] = 0.f; }
    if (i < NB * NROWP)      { g_sumSP[i] = 0.f; g_sumSIG[i] = 0.f; }
    if (i < NB * NT)         { g_tsum[i] = 0.f; }
}

// ---------------- kernel 1: class cost ----------------
__global__ void k_class(const float* __restrict__ logits,
                        const int* __restrict__ labels) {
    int b = blockIdx.x / NQ, n = blockIdx.x % NQ;
    int lane = threadIdx.x;
    __shared__ float sh[81];
    const float* L = logits + (size_t)(b * NQ + n) * 81;

    float x0 = L[lane];
    float x1 = (lane + 32 < 81) ? L[lane + 32] : -1e30f;
    float x2 = (lane + 64 < 81) ? L[lane + 64] : -1e30f;
    float m = fmaxf(x0, fmaxf(x1, x2));
    #pragma unroll
    for (int o = 16; o; o >>= 1) m = fmaxf(m, __shfl_xor_sync(0xffffffffu, m, o));

    float e0 = __expf(x0 - m);
    float e1 = (lane + 32 < 81) ? __expf(x1 - m) : 0.f;
    float e2 = (lane + 64 < 81) ? __expf(x2 - m) : 0.f;
    float s = e0 + e1 + e2;
    #pragma unroll
    for (int o = 16; o; o >>= 1) s += __shfl_xor_sync(0xffffffffu, s, o);

    sh[lane] = e0;
    if (lane + 32 < 81) sh[lane + 32] = e1;
    if (lane + 64 < 81) sh[lane + 64] = e2;
    __syncwarp();

    float inv = 1.0f / s;
    int lbl = labels[b * NT + lane];
    g_classT[(b * NT + lane) * NQ + n] = -sh[lbl] * inv;
}

// ---------------- kernel 2: target mask preprocess ----------------
__global__ __launch_bounds__(256) void k_tmask(const float* __restrict__ tgt) {
    int b = blockIdx.y;
    int p = blockIdx.x * 256 + threadIdx.x;
    int h = p >> 8, wc = p & 255;
    size_t base = ((size_t)b * NT) * 512 * 512 + (size_t)(2 * h) * 512 + 2 * wc;
    uint32_t word = 0;
    #pragma unroll
    for (int t = 0; t < 32; ++t) {
        float v = tgt[base + (size_t)t * 512 * 512];
        word |= (v != 0.0f ? 1u : 0u) << t;
    }
    g_bits[b * HW + p] = word;

    int lane = threadIdx.x & 31;
    int cnt = 0;
    #pragma unroll
    for (int t = 0; t < 32; ++t) {
        unsigned m = __ballot_sync(0xffffffffu, (word >> t) & 1u);
        if (lane == t) cnt = __popc(m);
    }
    atomicAdd(&g_tsum[b * NT + lane], (float)cnt);
}

// ---------------- kernel 3: fused elementwise + dual bf16 MMA ----------------
__global__ __launch_bounds__(256) void k_main(const float* __restrict__ pm) {
    const int b = blockIdx.z, mt = blockIdx.y;
    const int warp = threadIdx.x >> 5, lane = threadIdx.x & 31;
    const int kstart = blockIdx.x * (HW / 16) + warp * (HW / 16 / 8);
    const int rq = lane >> 2;
    const int kq = (lane & 3) << 1;
    const int r_lo = mt * 16 + rq, r_hi = r_lo + 8;
    const int rl = min(r_lo, NQ - 1), rh = min(r_hi, NQ - 1);

    const float*    pmb = pm + (size_t)b * NQ * HW;
    const uint32_t* bw  = g_bits + b * HW;

    float cpm[4][4], csg[4][4];
    #pragma unroll
    for (int i = 0; i < 4; ++i)
        #pragma unroll
        for (int j = 0; j < 4; ++j) { cpm[i][j] = 0.f; csg[i][j] = 0.f; }

    float ssp0 = 0.f, ssp1 = 0.f, ssg0 = 0.f, ssg1 = 0.f;

    #pragma unroll 4
    for (int it = 0; it < 32; ++it) {
        int k0 = kstart + it * 16 + kq;
        float2 x00 = *(const float2*)(pmb + (size_t)rl * HW + k0);
        float2 x10 = *(const float2*)(pmb + (size_t)rh * HW + k0);
        float2 x01 = *(const float2*)(pmb + (size_t)rl * HW + k0 + 8);
        float2 x11 = *(const float2*)(pmb + (size_t)rh * HW + k0 + 8);

        float s00a, s00b, s10a, s10b, s01a, s01b, s11a, s11b;
        float p00a, p00b, p10a, p10b, p01a, p01b, p11a, p11b;
        elem_math(x00.x, s00a, p00a); elem_math(x00.y, s00b, p00b);
        elem_math(x10.x, s10a, p10a); elem_math(x10.y, s10b, p10b);
        elem_math(x01.x, s01a, p01a); elem_math(x01.y, s01b, p01b);
        elem_math(x11.x, s11a, p11a); elem_math(x11.y, s11b, p11b);

        ssp0 += (p00a + p00b) + (p01a + p01b);
        ssp1 += (p10a + p10b) + (p11a + p11b);
        ssg0 += (s00a + s00b) + (s01a + s01b);
        ssg1 += (s10a + s10b) + (s11a + s11b);

        uint32_t apm[4] = { pack_bf16(x00.y, x00.x), pack_bf16(x10.y, x10.x),
                            pack_bf16(x01.y, x01.x), pack_bf16(x11.y, x11.x) };
        uint32_t asg[4] = { pack_bf16(s00b, s00a), pack_bf16(s10b, s10a),
                            pack_bf16(s01b, s01a), pack_bf16(s11b, s11a) };

        // hoist variable shift once; per-nt extraction uses constant-shift BFE
        uint32_t t0 = bw[k0] >> rq, t1 = bw[k0 + 1] >> rq;
        uint32_t t2 = bw[k0 + 8] >> rq, t3 = bw[k0 + 9] >> rq;
        #pragma unroll
        for (int nt = 0; nt < 4; ++nt) {
            uint32_t b0 = ((t0 >> (8 * nt)) & 1u) * 0x3F80u |
                          ((t1 >> (8 * nt)) & 1u) * 0x3F800000u;
            uint32_t b1 = ((t2 >> (8 * nt)) & 1u) * 0x3F80u |
                          ((t3 >> (8 * nt)) & 1u) * 0x3F800000u;
            mma_bf16(cpm[nt], apm, b0, b1);
            mma_bf16(csg[nt], asg, b0, b1);
        }
    }

    int base_lo = (b * NROWP + r_lo) * NT;
    int base_hi = (b * NROWP + r_hi) * NT;
    #pragma unroll
    for (int nt = 0; nt < 4; ++nt) {
        int c = nt * 8 + kq;
        atomicAdd(&g_dotPM[base_lo + c],     cpm[nt][0]);
        atomicAdd(&g_dotPM[base_lo + c + 1], cpm[nt][1]);
        atomicAdd(&g_dotPM[base_hi + c],     cpm[nt][2]);
        atomicAdd(&g_dotPM[base_hi + c + 1], cpm[nt][3]);
        atomicAdd(&g_dotSIG[base_lo + c],     csg[nt][0]);
        atomicAdd(&g_dotSIG[base_lo + c + 1], csg[nt][1]);
        atomicAdd(&g_dotSIG[base_hi + c],     csg[nt][2]);
        atomicAdd(&g_dotSIG[base_hi + c + 1], csg[nt][3]);
    }
    atomicAdd(&g_sumSP[b * NROWP + r_lo],  ssp0);
    atomicAdd(&g_sumSP[b * NROWP + r_hi],  ssp1);
    atomicAdd(&g_sumSIG[b * NROWP + r_lo], ssg0);
    atomicAdd(&g_sumSIG[b * NROWP + r_hi], ssg1);
}

// ---------------- kernel 4: assemble transposed cost matrix ----------------
__global__ void k_cost() {
    int i = blockIdx.x * 256 + threadIdx.x;
    if (i >= NB * NT * NQ) return;
    int n = i % NQ;
    int t = (i / NQ) % NT;
    int b = i / (NQ * NT);
    float spm  = g_sumSP[b * NROWP + n] * (1.0f / HW);
    float dpm  = g_dotPM[(b * NROWP + n) * NT + t] * (1.0f / HW);
    float dsg  = g_dotSIG[(b * NROWP + n) * NT + t];
    float den  = g_sumSIG[b * NROWP + n] + g_tsum[b * NT + t] + 1.0f;
    float dice = 1.0f - (2.0f * dsg + 1.0f) / den;
    g_costT[i] = g_classT[i] + (spm - dpm) + dice;
}

// ---------------- kernel 5: Hungarian (JV), one warp per batch ----------------
// Cost in shared; v/minv/way/p in registers (4 col slots per lane, static
// indexing only); u in shared; fp32; argmin via ordered-key redux + ballot.
__global__ void k_hung(float* __restrict__ out) {
    const int b = blockIdx.x;
    const int lane = threadIdx.x;
    __shared__ float Cs[NT * NQ];
    __shared__ float u[NT + 1];
    __shared__ int   psh[NQ + 1];

    for (int idx = lane; idx < NT * NQ; idx += 32)
        Cs[idx] = g_costT[b * NT * NQ + idx];
    if (lane <= NT) u[lane] = 0.f;
    __syncwarp();

    // lane owns cols j = lane, 32+lane, 64+lane, 96+lane (j valid in 0..100)
    float v0 = 0.f, v1 = 0.f, v2 = 0.f, v3 = 0.f;
    int   p0 = 0, p1 = 0, p2 = 0, p3 = 0;
    int   w0 = 0, w1 = 0, w2 = 0, w3 = 0;

    for (int i = 1; i <= NT; ++i) {
        float m0 = 1e30f, m1 = 1e30f, m2 = 1e30f, m3 = 1e30f;
        unsigned usedm = 0;
        if (lane == 0) p0 = i;
        int j0 = 0;

        while (true) {
            if ((j0 & 31) == lane) usedm |= 1u << (j0 >> 5);
            int i0 = __shfl_sync(0xffffffffu, sel4i(p0, p1, p2, p3, j0 >> 5), j0 & 31);
            float ui0 = u[i0];
            const float* Crow = Cs + (i0 - 1) * NQ;

            uint32_t bk = 0xFFFFFFFFu; int bj = 127;
            if (lane >= 1 && !(usedm & 1u)) {                 // j = lane
                float cur = Crow[lane - 1] - ui0 - v0;
                if (cur < m0) { m0 = cur; w0 = j0; }
                uint32_t k = fkey(m0);
                if (k < bk) { bk = k; bj = lane; }
            }
            if (!(usedm & 2u)) {                              // j = 32+lane
                float cur = Crow[31 + lane] - ui0 - v1;
                if (cur < m1) { m1 = cur; w1 = j0; }
                uint32_t k = fkey(m1);
                if (k < bk) { bk = k; bj = 32 + lane; }
            }
            if (!(usedm & 4u)) {                              // j = 64+lane
                float cur = Crow[63 + lane] - ui0 - v2;
                if (cur < m2) { m2 = cur; w2 = j0; }
                uint32_t k = fkey(m2);
                if (k < bk) { bk = k; bj = 64 + lane; }
            }
            if (lane <= 4 && !(usedm & 8u)) {                 // j = 96+lane <= 100
                float cur = Crow[95 + lane] - ui0 - v3;
                if (cur < m3) { m3 = cur; w3 = j0; }
                uint32_t k = fkey(m3);
                if (k < bk) { bk = k; bj = 96 + lane; }
            }

            uint32_t kmin = __reduce_min_sync(0xffffffffu, bk);
            unsigned ball = __ballot_sync(0xffffffffu, bk == kmin);
            int src = __ffs(ball) - 1;
            int j1  = __shfl_sync(0xffffffffu, bj, src);
            float delta = fkey_inv(kmin);

            if (usedm & 1u) { u[p0] += delta; v0 -= delta; } else m0 -= delta;
            if (usedm & 2u) { u[p1] += delta; v1 -= delta; } else m1 -= delta;
            if (usedm & 4u) { u[p2] += delta; v2 -= delta; } else m2 -= delta;
            if (usedm & 8u) { u[p3] += delta; v3 -= delta; } else m3 -= delta;
            __syncwarp();

            j0 = j1;
            int pj0 = __shfl_sync(0xffffffffu, sel4i(p0, p1, p2, p3, j0 >> 5), j0 & 31);
            if (pj0 == 0) break;
        }

        // augment along 'way' chain (lockstep; uniform j0)
        while (j0 != 0) {
            int j1  = __shfl_sync(0xffffffffu, sel4i(w0, w1, w2, w3, j0 >> 5), j0 & 31);
            int pj1 = __shfl_sync(0xffffffffu, sel4i(p0, p1, p2, p3, j1 >> 5), j1 & 31);
            if ((j0 & 31) == lane) {
                int s = j0 >> 5;
                if (s == 0) p0 = pj1; else if (s == 1) p1 = pj1;
                else if (s == 2) p2 = pj1; else p3 = pj1;
            }
            j0 = j1;
        }
        __syncwarp();
    }

    psh[lane] = p0;
    psh[32 + lane] = p1;
    psh[64 + lane] = p2;
    if (lane <= 4) psh[96 + lane] = p3;
    __syncwarp();

    if (lane == 0) {
        int k = 0;
        for (int j = 1; j <= NQ; ++j) {
            if (psh[j]) {
                out[b * NT + k]           = (float)(j - 1);      // src query idx
                out[NB * NT + b * NT + k] = (float)(psh[j] - 1); // tgt idx
                ++k;
            }
        }
    }
}

// ---------------- launch ----------------
extern "C" void kernel_launch(void* const* d_in, const int* in_sizes, int n_in,
                              void* d_out, int out_size) {
    const float* logits = nullptr;
    const float* pmask  = nullptr;
    const float* tmask  = nullptr;
    const int*   labels = nullptr;

    for (int i = 0; i < n_in; ++i) {
        switch (in_sizes[i]) {
            case 64800:    logits = (const float*)d_in[i]; break;
            case 52428800: pmask  = (const float*)d_in[i]; break;
            case 256:      labels = (const int*)d_in[i];   break;
            default:
                if (in_sizes[i] == 67108864) tmask = (const float*)d_in[i];
                break;
        }
    }
    float* out = (float*)d_out;

    k_zero<<<(NB * NROWP * NT + 255) / 256, 256>>>();
    k_class<<<NB * NQ, 32>>>(logits, labels);
    k_tmask<<<dim3(HW / 256, NB), 256>>>(tmask);
    k_main<<<dim3(16, 7, NB), 256>>>(pmask);
    k_cost<<<(NB * NT * NQ + 255) / 256, 256>>>();
    k_hung<<<NB, 32>>>(out);
}